// round 6
// baseline (speedup 1.0000x reference)
#include <cuda_runtime.h>
#include <cuda_bf16.h>
#include <cstdint>

// qpNet: z = max(-(x @ W^T + b), -1/EPS), EPS=1e-3  =>  z = max(-h, -1000)
// x: [B,5] f32, W: [5,5] f32, b: [5] f32, out: [B,5] f32. B = 4194304.
//
// R6: persistent 608-CTA grid, double-buffered 1D bulk-TMA pipeline.
// Each CTA grid-strides over 1024-row tiles (20 KB). While computing tile i
// from buf (i&1), the TMA load of tile i+2 is in flight and the store of
// tile i-2 has been drained (wait_group.read 2) before buffer reuse.

#define NEG_CLAMP   (-1000.0f)   // -1/EPS
#define TILE_FLOATS 5120         // 1024 rows * 5
#define TILE_BYTES  20480u

__global__ __launch_bounds__(256) void qp_kernel(
    const float* __restrict__ x,
    const float* __restrict__ W,
    const float* __restrict__ b,
    float* __restrict__ out,
    int ntiles)
{
    __shared__ alignas(128) float4 buf[2][1280];        // 2 x 20 KB
    __shared__ alignas(8)   unsigned long long mbar[2];

    const int tid = threadIdx.x;
    const unsigned mb0 = (unsigned)__cvta_generic_to_shared(&mbar[0]);
    const unsigned sb0 = (unsigned)__cvta_generic_to_shared(&buf[0][0]);
    const unsigned sb1 = (unsigned)__cvta_generic_to_shared(&buf[1][0]);

    if (tid == 0) {
        asm volatile("mbarrier.init.shared.b64 [%0], %1;" :: "r"(mb0),     "r"(1u));
        asm volatile("mbarrier.init.shared.b64 [%0], %1;" :: "r"(mb0 + 8), "r"(1u));
    }
    __syncthreads();

    const int grid = gridDim.x;
    const int t0   = blockIdx.x;

    // ---- prologue: prefetch first two tiles ----
    if (tid == 0) {
        long long t = t0;
        if (t < ntiles) {
            asm volatile("mbarrier.arrive.expect_tx.shared.b64 _, [%0], %1;"
                         :: "r"(mb0), "r"(TILE_BYTES) : "memory");
            asm volatile("cp.async.bulk.shared::cta.global.mbarrier::complete_tx::bytes "
                         "[%0], [%1], %2, [%3];"
                         :: "r"(sb0), "l"((unsigned long long)(uintptr_t)(x + t * TILE_FLOATS)),
                            "r"(TILE_BYTES), "r"(mb0) : "memory");
        }
        t = t0 + grid;
        if (t < ntiles) {
            asm volatile("mbarrier.arrive.expect_tx.shared.b64 _, [%0], %1;"
                         :: "r"(mb0 + 8), "r"(TILE_BYTES) : "memory");
            asm volatile("cp.async.bulk.shared::cta.global.mbarrier::complete_tx::bytes "
                         "[%0], [%1], %2, [%3];"
                         :: "r"(sb1), "l"((unsigned long long)(uintptr_t)(x + t * TILE_FLOATS)),
                            "r"(TILE_BYTES), "r"(mb0 + 8) : "memory");
        }
    }

    // ---- W [5,5] + b [5] while first TMA is in flight ----
    float w[5][5], bb[5];
    {
        const float4* W4 = reinterpret_cast<const float4*>(W);
        float4 a0 = __ldg(W4 + 0);
        float4 a1 = __ldg(W4 + 1);
        float4 a2 = __ldg(W4 + 2);
        float4 a3 = __ldg(W4 + 3);
        float4 a4 = __ldg(W4 + 4);
        float4 a5 = __ldg(W4 + 5);
        float  a6 = __ldg(W + 24);
        w[0][0]=a0.x; w[0][1]=a0.y; w[0][2]=a0.z; w[0][3]=a0.w; w[0][4]=a1.x;
        w[1][0]=a1.y; w[1][1]=a1.z; w[1][2]=a1.w; w[1][3]=a2.x; w[1][4]=a2.y;
        w[2][0]=a2.z; w[2][1]=a2.w; w[2][2]=a3.x; w[2][3]=a3.y; w[2][4]=a3.z;
        w[3][0]=a3.w; w[3][1]=a4.x; w[3][2]=a4.y; w[3][3]=a4.z; w[3][4]=a4.w;
        w[4][0]=a5.x; w[4][1]=a5.y; w[4][2]=a5.z; w[4][3]=a5.w; w[4][4]=a6;
        const float4* b4 = reinterpret_cast<const float4*>(b);
        float4 bv = __ldg(b4);
        bb[0]=bv.x; bb[1]=bv.y; bb[2]=bv.z; bb[3]=bv.w; bb[4]=__ldg(b + 4);
    }

    int phase0 = 0, phase1 = 0;

    for (long long t = t0, i = 0; t < ntiles; t += grid, i++) {
        const int      bsel = (int)(i & 1);
        const unsigned mb   = mb0 + 8u * bsel;
        const int      ph   = bsel ? phase1 : phase0;
        float4* __restrict__ tile = &buf[bsel][0];

        // ---- wait for this tile's TMA load (acquire: LDS follows) ----
        asm volatile(
            "{\n\t"
            ".reg .pred P;\n\t"
            "WAIT_%=:\n\t"
            "mbarrier.try_wait.parity.acquire.cta.shared::cta.b64 P, [%0], %1, 0x989680;\n\t"
            "@P bra DONE_%=;\n\t"
            "bra WAIT_%=;\n\t"
            "DONE_%=:\n\t"
            "}"
            :: "r"(mb), "r"(ph) : "memory");
        if (bsel) phase1 ^= 1; else phase0 ^= 1;

        // ---- read own 4 rows via 5x LDS.128 (conflict-free, 80B stride) ----
        float4 v[5];
#pragma unroll
        for (int k = 0; k < 5; k++)
            v[k] = tile[5 * tid + k];

        float xr[4][5];
        xr[0][0]=v[0].x; xr[0][1]=v[0].y; xr[0][2]=v[0].z; xr[0][3]=v[0].w; xr[0][4]=v[1].x;
        xr[1][0]=v[1].y; xr[1][1]=v[1].z; xr[1][2]=v[1].w; xr[1][3]=v[2].x; xr[1][4]=v[2].y;
        xr[2][0]=v[2].z; xr[2][1]=v[2].w; xr[2][2]=v[3].x; xr[2][3]=v[3].y; xr[2][4]=v[3].z;
        xr[3][0]=v[3].w; xr[3][1]=v[4].x; xr[3][2]=v[4].y; xr[3][3]=v[4].z; xr[3][4]=v[4].w;

        float zr[4][5];
#pragma unroll
        for (int r = 0; r < 4; r++) {
#pragma unroll
            for (int j = 0; j < 5; j++) {
                float h = bb[j];
#pragma unroll
                for (int k = 0; k < 5; k++)
                    h = fmaf(xr[r][k], w[j][k], h);
                zr[r][j] = fmaxf(-h, NEG_CLAMP);
            }
        }

        // Write z back to own slots (within-thread hazard only).
        tile[5 * tid + 0] = make_float4(zr[0][0], zr[0][1], zr[0][2], zr[0][3]);
        tile[5 * tid + 1] = make_float4(zr[0][4], zr[1][0], zr[1][1], zr[1][2]);
        tile[5 * tid + 2] = make_float4(zr[1][3], zr[1][4], zr[2][0], zr[2][1]);
        tile[5 * tid + 3] = make_float4(zr[2][2], zr[2][3], zr[2][4], zr[3][0]);
        tile[5 * tid + 4] = make_float4(zr[3][1], zr[3][2], zr[3][3], zr[3][4]);

        __syncthreads();   // all z in smem before bulk store reads it

        if (tid == 0) {
            const unsigned sb = bsel ? sb1 : sb0;
            asm volatile("fence.proxy.async.shared::cta;" ::: "memory");
            asm volatile("cp.async.bulk.global.shared::cta.bulk_group [%0], [%1], %2;"
                         :: "l"((unsigned long long)(uintptr_t)(out + t * TILE_FLOATS)),
                            "r"(sb), "r"(TILE_BYTES) : "memory");
            asm volatile("cp.async.bulk.commit_group;" ::: "memory");

            const long long tn = t + 2 * grid;
            if (tn < ntiles) {
                // Buffer reuse: store issued from this buf 2 iters ago must be
                // read-done. After committing store i, <=2 outstanding means
                // store i-2 has drained.
                asm volatile("cp.async.bulk.wait_group.read 2;" ::: "memory");
                asm volatile("mbarrier.arrive.expect_tx.shared.b64 _, [%0], %1;"
                             :: "r"(mb), "r"(TILE_BYTES) : "memory");
                asm volatile("cp.async.bulk.shared::cta.global.mbarrier::complete_tx::bytes "
                             "[%0], [%1], %2, [%3];"
                             :: "r"(sb), "l"((unsigned long long)(uintptr_t)(x + tn * TILE_FLOATS)),
                                "r"(TILE_BYTES), "r"(mb) : "memory");
            }
        }
        // No extra barrier: next iteration computes on the OTHER buffer, and
        // reuse of this buffer is gated by its mbarrier (new load) which tid0
        // issues only after the store drained.
    }

    // CTA must not exit while bulk stores still read its smem.
    if (tid == 0)
        asm volatile("cp.async.bulk.wait_group.read 0;" ::: "memory");
}

extern "C" void kernel_launch(void* const* d_in, const int* in_sizes, int n_in,
                              void* d_out, int out_size)
{
    const float* x = (const float*)d_in[0];   // [B,5]
    const float* W = (const float*)d_in[1];   // [5,5]
    const float* b = (const float*)d_in[2];   // [5]
    float* out = (float*)d_out;               // [B,5]

    const long long B = in_sizes[0] / 5;      // 4194304
    const int ntiles = (int)(B / 1024);       // 4096, exact cover

    const int threads = 256;
    const int blocks = 152 * 4;               // persistent: 4 CTAs/SM x 152 SMs

    qp_kernel<<<blocks, threads>>>(x, W, b, out, ntiles);
}